// round 11
// baseline (speedup 1.0000x reference)
#include <cuda_runtime.h>
#include <cuda_bf16.h>
#include <cstdint>

#define NUM_HEADS 12
#define HEAD_DIM  64
#define SEQ       2048
#define BATCH     2
#define EMB       768
#define SEG       256
#define KDIM      768

// Scratch — EXACT R4/R8/R9 set (proven to pass the allocation guard)
__device__ float g_q[BATCH*NUM_HEADS*SEQ*HEAD_DIM];
__device__ float g_k[BATCH*NUM_HEADS*SEQ*HEAD_DIM];
__device__ float g_v[BATCH*NUM_HEADS*SEQ*HEAD_DIM];
__device__ float g_ctx[BATCH*SEQ*EMB];

// ===========================================================================
// Warp-level MMA helpers (compute_100-safe: sm_80-era PTX)
// ===========================================================================
__device__ __forceinline__ uint32_t smem_u32(const void* p) {
  uint32_t a;
  asm("{ .reg .u64 t; cvta.to.shared.u64 t, %1; cvt.u32.u64 %0, t; }" : "=r"(a) : "l"(p));
  return a;
}
__device__ __forceinline__ void ldsm4(uint32_t* r, uint32_t addr) {
  asm volatile("ldmatrix.sync.aligned.m8n8.x4.shared.b16 {%0,%1,%2,%3}, [%4];"
               : "=r"(r[0]), "=r"(r[1]), "=r"(r[2]), "=r"(r[3]) : "r"(addr));
}
__device__ __forceinline__ void mma_bf16(float* d, const uint32_t* a,
                                         uint32_t b0, uint32_t b1) {
  asm volatile(
      "mma.sync.aligned.m16n8k16.row.col.f32.bf16.bf16.f32 "
      "{%0,%1,%2,%3}, {%4,%5,%6,%7}, {%8,%9}, {%0,%1,%2,%3};"
      : "+f"(d[0]), "+f"(d[1]), "+f"(d[2]), "+f"(d[3])
      : "r"(a[0]), "r"(a[1]), "r"(a[2]), "r"(a[3]), "r"(b0), "r"(b1));
}

#define SWZ(off) ((off) ^ (((off) >> 3) & 0x70))

__device__ __forceinline__ uint32_t pack2(float a, float b) {
  __nv_bfloat162 p = __halves2bfloat162(__float2bfloat16(a), __float2bfloat16(b));
  return *reinterpret_cast<uint32_t*>(&p);
}

// ===========================================================================
// GEMM v4: R8 structure (256 thr, 4x2 warp grid, 32x64 tiles, register
// prefetch) + DOUBLE-BUFFERED smem, ONE sync per chunk: cvt+STS of chunk
// c+1 overlaps the MMA phase of chunk c across warps.
// mode 0: QKV (blockIdx.z selects q/k/v, scatter to (B,H,S,D))
// mode 1: out projection (row-major to dout)
// ===========================================================================
#define GK      64
#define NCHUNK  (KDIM / GK)            // 12
#define OFF_AHI 0
#define OFF_ALO 16384
#define OFF_BHI 32768
#define OFF_BLO 49152
#define STAGE_B 65536
#define GEMM_SMEM (2 * STAGE_B)        // 131072

__global__ __launch_bounds__(256) void gemm_hmma_kernel(
    const float* __restrict__ A0,
    const float* __restrict__ W0, const float* __restrict__ b0,
    const float* __restrict__ W1, const float* __restrict__ b1,
    const float* __restrict__ W2, const float* __restrict__ b2,
    float* __restrict__ dout, int mode) {
  extern __shared__ char sm[];
  const uint32_t sbase = smem_u32(sm);
  const int tid  = threadIdx.x;
  const int wid  = tid >> 5;
  const int lane = tid & 31;
  const int m0 = blockIdx.y * 128;
  const int n0 = blockIdx.x * 128;
  const int z  = blockIdx.z;

  const float* A    = (mode == 1) ? g_ctx : A0;
  const float* W    = (z == 0) ? W0 : (z == 1) ? W1 : W2;
  const float* bias = (z == 0) ? b0 : (z == 1) ? b1 : b2;
  float* outp = (mode == 1) ? dout : ((z == 0) ? g_q : (z == 1) ? g_k : g_v);

  const int r  = tid >> 1;
  const int cb = (tid & 1) * 32;
  const float* Ap = A + (size_t)(m0 + r) * KDIM + cb;
  const float* Wp = W + (size_t)(n0 + r) * KDIM + cb;
  const uint32_t swr = SWZ((uint32_t)(r * 128 + cb * 2));  // base row offset (u=0)

  const int mw = (wid >> 1) * 32;
  const int nw = (wid & 1) * 64;
  const int lrow = lane & 15;
  const int lkb  = (lane >> 4) * 16;

  float acc[16][4];
#pragma unroll
  for (int i = 0; i < 16; i++)
#pragma unroll
    for (int j = 0; j < 4; j++) acc[i][j] = 0.f;

  // ---- prologue: LDG chunk 0 -> regs, cvt+STS -> buf 0 ----
  float4 pa[8], pw[8];
#pragma unroll
  for (int u = 0; u < 8; u++) {
    pa[u] = *(const float4*)(Ap + u * 4);
    pw[u] = *(const float4*)(Wp + u * 4);
  }
  {
    char* sbuf = sm;  // buffer 0
#pragma unroll
    for (int u = 0; u < 8; u++) {
      const float4 av = pa[u];
      const float4 wv = pw[u];
      const uint32_t sw = SWZ((uint32_t)(r * 128 + (cb + u * 4) * 2));
      float ahx = __bfloat162float(__float2bfloat16(av.x));
      float ahy = __bfloat162float(__float2bfloat16(av.y));
      float ahz = __bfloat162float(__float2bfloat16(av.z));
      float ahw = __bfloat162float(__float2bfloat16(av.w));
      *(uint2*)(sbuf + OFF_AHI + sw) = make_uint2(pack2(ahx, ahy), pack2(ahz, ahw));
      *(uint2*)(sbuf + OFF_ALO + sw) =
          make_uint2(pack2(av.x - ahx, av.y - ahy), pack2(av.z - ahz, av.w - ahw));
      float whx = __bfloat162float(__float2bfloat16(wv.x));
      float why = __bfloat162float(__float2bfloat16(wv.y));
      float whz = __bfloat162float(__float2bfloat16(wv.z));
      float whw = __bfloat162float(__float2bfloat16(wv.w));
      *(uint2*)(sbuf + OFF_BHI + sw) = make_uint2(pack2(whx, why), pack2(whz, whw));
      *(uint2*)(sbuf + OFF_BLO + sw) =
          make_uint2(pack2(wv.x - whx, wv.y - why), pack2(wv.z - whz, wv.w - whw));
    }
  }

  for (int c = 0; c < NCHUNK; c++) {
    __syncthreads();                       // buf[c&1] fully staged

    // ---- prefetch chunk c+1 (retires behind MMA phase) ----
    if (c + 1 < NCHUNK) {
#pragma unroll
      for (int u = 0; u < 8; u++) {
        pa[u] = *(const float4*)(Ap + (c + 1) * GK + u * 4);
        pw[u] = *(const float4*)(Wp + (c + 1) * GK + u * 4);
      }
    }

    // ---- compute chunk c from buf[c&1] ----
    const uint32_t cbuf = sbase + (uint32_t)(c & 1) * STAGE_B;
#pragma unroll
    for (int ks = 0; ks < 4; ks++) {
      const uint32_t koff = (uint32_t)(ks * 32 + lkb);
      uint32_t ah[2][4], al[2][4];
#pragma unroll
      for (int mi = 0; mi < 2; mi++) {
        const uint32_t off = (uint32_t)((mw + mi * 16 + lrow) * 128) + koff;
        ldsm4(ah[mi], cbuf + OFF_AHI + SWZ(off));
        ldsm4(al[mi], cbuf + OFF_ALO + SWZ(off));
      }
      uint32_t bh[4][4], bl[4][4];
#pragma unroll
      for (int nb = 0; nb < 4; nb++) {
        const uint32_t off = (uint32_t)((nw + nb * 16 + lrow) * 128) + koff;
        ldsm4(bh[nb], cbuf + OFF_BHI + SWZ(off));
        ldsm4(bl[nb], cbuf + OFF_BLO + SWZ(off));
      }
#pragma unroll
      for (int ni = 0; ni < 8; ni++) {
        const int nb = ni >> 1, sel = ni & 1;
        const uint32_t bh0 = bh[nb][sel], bh1 = bh[nb][2 + sel];
        const uint32_t bl0 = bl[nb][sel], bl1 = bl[nb][2 + sel];
#pragma unroll
        for (int mi = 0; mi < 2; mi++) {
          mma_bf16(acc[mi * 8 + ni], ah[mi], bh0, bh1);
          mma_bf16(acc[mi * 8 + ni], ah[mi], bl0, bl1);
          mma_bf16(acc[mi * 8 + ni], al[mi], bh0, bh1);
        }
      }
    }

    // ---- cvt+STS chunk c+1 into buf[(c+1)&1] (no barrier before this:
    //      other warps may still be in MMA on buf[c&1] — different buffer)
    if (c + 1 < NCHUNK) {
      char* sbuf = sm + ((c + 1) & 1) * STAGE_B;
#pragma unroll
      for (int u = 0; u < 8; u++) {
        const float4 av = pa[u];
        const float4 wv = pw[u];
        const uint32_t sw = SWZ((uint32_t)(r * 128 + (cb + u * 4) * 2));
        float ahx = __bfloat162float(__float2bfloat16(av.x));
        float ahy = __bfloat162float(__float2bfloat16(av.y));
        float ahz = __bfloat162float(__float2bfloat16(av.z));
        float ahw = __bfloat162float(__float2bfloat16(av.w));
        *(uint2*)(sbuf + OFF_AHI + sw) = make_uint2(pack2(ahx, ahy), pack2(ahz, ahw));
        *(uint2*)(sbuf + OFF_ALO + sw) =
            make_uint2(pack2(av.x - ahx, av.y - ahy), pack2(av.z - ahz, av.w - ahw));
        float whx = __bfloat162float(__float2bfloat16(wv.x));
        float why = __bfloat162float(__float2bfloat16(wv.y));
        float whz = __bfloat162float(__float2bfloat16(wv.z));
        float whw = __bfloat162float(__float2bfloat16(wv.w));
        *(uint2*)(sbuf + OFF_BHI + sw) = make_uint2(pack2(whx, why), pack2(whz, whw));
        *(uint2*)(sbuf + OFF_BLO + sw) =
            make_uint2(pack2(wv.x - whx, wv.y - why), pack2(wv.z - whz, wv.w - whw));
      }
    }
  }

  // ---- epilogue: bias add + store ----
  const int er = lane >> 2;
  const int ec = (lane & 3) * 2;
#pragma unroll
  for (int mi = 0; mi < 2; mi++) {
#pragma unroll
    for (int rr = 0; rr < 2; rr++) {
      const int m = m0 + mw + mi * 16 + rr * 8 + er;
      if (mode == 1) {
        float* orow = outp + (size_t)m * EMB;
#pragma unroll
        for (int ni = 0; ni < 8; ni++) {
          const int n = n0 + nw + ni * 8 + ec;
          float2 v;
          v.x = acc[mi * 8 + ni][rr * 2 + 0] + bias[n];
          v.y = acc[mi * 8 + ni][rr * 2 + 1] + bias[n + 1];
          *(float2*)(orow + n) = v;
        }
      } else {
        const int b = m >> 11;
        const int s = m & 2047;
#pragma unroll
        for (int ni = 0; ni < 8; ni++) {
          const int n = n0 + nw + ni * 8 + ec;
          const int h = n >> 6;
          const int d = n & 63;
          float2 v;
          v.x = acc[mi * 8 + ni][rr * 2 + 0] + bias[n];
          v.y = acc[mi * 8 + ni][rr * 2 + 1] + bias[n + 1];
          *(float2*)(outp + (((size_t)b * NUM_HEADS + h) * SEQ + s) * HEAD_DIM + d) = v;
        }
      }
    }
  }
}

// ===========================================================================
// HMMA attention (R9-proven, untouched). Block-diagonal over 256-token segs.
// ===========================================================================
#define AT_QHI  0
#define AT_QLO  8192
#define AT_KHI  16384
#define AT_KLO  49152
#define AT_PHI  81920
#define AT_PLO  114688
#define AT_VHI  147456
#define AT_VLO  180224
#define AT_REDM 212992
#define AT_REDS 214016
#define AT_RINV 215040
#define ATTN_SMEM 215296

__global__ __launch_bounds__(256) void attn_kernel() {
  extern __shared__ char sm[];
  const uint32_t sbase = smem_u32(sm);
  float* REDM = (float*)(sm + AT_REDM);
  float* REDS = (float*)(sm + AT_REDS);
  float* RINV = (float*)(sm + AT_RINV);

  const int tid  = threadIdx.x;
  const int wid  = tid >> 5;
  const int lane = tid & 31;
  int bx = blockIdx.x;
  const int qt  = bx & 3;   bx >>= 2;
  const int seg = bx & 7;   bx >>= 3;
  const int hh  = bx % NUM_HEADS;
  const int bb  = bx / NUM_HEADS;

  const size_t head_off = (((size_t)bb*NUM_HEADS + hh)*SEQ + seg*SEG) * HEAD_DIM;
  const float* qbase = g_q + head_off + (size_t)qt*64*HEAD_DIM;
  const float* kbase = g_k + head_off;
  const float* vbase = g_v + head_off;

  {
    const int r  = tid >> 2;
    const int c0 = (tid & 3) * 16;
#pragma unroll
    for (int u = 0; u < 4; u++) {
      float4 v = *(const float4*)(qbase + r * 64 + c0 + u * 4);
      v.x *= 0.125f; v.y *= 0.125f; v.z *= 0.125f; v.w *= 0.125f;
      const uint32_t sw = SWZ((uint32_t)(r * 128 + (c0 + u * 4) * 2));
      float hx = __bfloat162float(__float2bfloat16(v.x));
      float hy = __bfloat162float(__float2bfloat16(v.y));
      float hz = __bfloat162float(__float2bfloat16(v.z));
      float hw = __bfloat162float(__float2bfloat16(v.w));
      *(uint2*)(sm + AT_QHI + sw) = make_uint2(pack2(hx, hy), pack2(hz, hw));
      *(uint2*)(sm + AT_QLO + sw) =
          make_uint2(pack2(v.x - hx, v.y - hy), pack2(v.z - hz, v.w - hw));
    }
  }
  {
    const int j = tid;
#pragma unroll
    for (int u = 0; u < 16; u++) {
      float4 v = *(const float4*)(kbase + j * 64 + u * 4);
      const uint32_t sw = SWZ((uint32_t)(j * 128 + u * 8));
      float hx = __bfloat162float(__float2bfloat16(v.x));
      float hy = __bfloat162float(__float2bfloat16(v.y));
      float hz = __bfloat162float(__float2bfloat16(v.z));
      float hw = __bfloat162float(__float2bfloat16(v.w));
      *(uint2*)(sm + AT_KHI + sw) = make_uint2(pack2(hx, hy), pack2(hz, hw));
      *(uint2*)(sm + AT_KLO + sw) =
          make_uint2(pack2(v.x - hx, v.y - hy), pack2(v.z - hz, v.w - hw));
    }
  }
  {
    const int j = tid;
    const uint32_t pbase = (uint32_t)(j >> 6) * 8192;
    const int jc = (j & 63) * 2;
#pragma unroll
    for (int u = 0; u < 16; u++) {
      float4 v = *(const float4*)(vbase + j * 64 + u * 4);
      float f[4] = {v.x, v.y, v.z, v.w};
#pragma unroll
      for (int e = 0; e < 4; e++) {
        const int d = u * 4 + e;
        const uint32_t sw = SWZ((uint32_t)(d * 128 + jc));
        float hi = __bfloat162float(__float2bfloat16(f[e]));
        *(__nv_bfloat16*)(sm + AT_VHI + pbase + sw) = __float2bfloat16(hi);
        *(__nv_bfloat16*)(sm + AT_VLO + pbase + sw) = __float2bfloat16(f[e] - hi);
      }
    }
  }
  __syncthreads();

  const int mw = (wid >> 2) * 32;
  const int nw = (wid & 3) * 64;
  const int lrow = lane & 15;
  const int lkb  = (lane >> 4) * 16;

  float acc[16][4];
#pragma unroll
  for (int i = 0; i < 16; i++)
#pragma unroll
    for (int j = 0; j < 4; j++) acc[i][j] = 0.f;

#pragma unroll
  for (int ks = 0; ks < 4; ks++) {
    const uint32_t koff = (uint32_t)(ks * 32 + lkb);
    uint32_t ah[2][4], al[2][4];
#pragma unroll
    for (int mi = 0; mi < 2; mi++) {
      const uint32_t off = (uint32_t)((mw + mi * 16 + lrow) * 128) + koff;
      ldsm4(ah[mi], sbase + AT_QHI + SWZ(off));
      ldsm4(al[mi], sbase + AT_QLO + SWZ(off));
    }
    uint32_t bh[4][4], bl[4][4];
#pragma unroll
    for (int nb = 0; nb < 4; nb++) {
      const uint32_t off = (uint32_t)((nw + nb * 16 + lrow) * 128) + koff;
      ldsm4(bh[nb], sbase + AT_KHI + SWZ(off));
      ldsm4(bl[nb], sbase + AT_KLO + SWZ(off));
    }
#pragma unroll
    for (int ni = 0; ni < 8; ni++) {
      const int nb = ni >> 1, sel = ni & 1;
      const uint32_t bh0 = bh[nb][sel], bh1 = bh[nb][2 + sel];
      const uint32_t bl0 = bl[nb][sel], bl1 = bl[nb][2 + sel];
#pragma unroll
      for (int mi = 0; mi < 2; mi++) {
        mma_bf16(acc[mi * 8 + ni], ah[mi], bh0, bh1);
        mma_bf16(acc[mi * 8 + ni], ah[mi], bl0, bl1);
        mma_bf16(acc[mi * 8 + ni], al[mi], bh0, bh1);
      }
    }
  }

  const int er = lane >> 2;
  const int ec = (lane & 3) * 2;
  const int wcol = wid & 3;

#pragma unroll
  for (int mi = 0; mi < 2; mi++)
#pragma unroll
    for (int rr = 0; rr < 2; rr++) {
      float m = -1e30f;
#pragma unroll
      for (int ni = 0; ni < 8; ni++) {
        m = fmaxf(m, acc[mi * 8 + ni][rr * 2 + 0]);
        m = fmaxf(m, acc[mi * 8 + ni][rr * 2 + 1]);
      }
      m = fmaxf(m, __shfl_xor_sync(0xffffffffu, m, 1));
      m = fmaxf(m, __shfl_xor_sync(0xffffffffu, m, 2));
      if ((lane & 3) == 0)
        REDM[wcol * 64 + mw + mi * 16 + rr * 8 + er] = m;
    }
  __syncthreads();

  const uint32_t ppan = (uint32_t)wcol * 8192;
#pragma unroll
  for (int mi = 0; mi < 2; mi++)
#pragma unroll
    for (int rr = 0; rr < 2; rr++) {
      const int m = mw + mi * 16 + rr * 8 + er;
      float fm = fmaxf(fmaxf(REDM[m], REDM[64 + m]),
                       fmaxf(REDM[128 + m], REDM[192 + m]));
      float s = 0.f;
#pragma unroll
      for (int ni = 0; ni < 8; ni++) {
        float e0 = __expf(acc[mi * 8 + ni][rr * 2 + 0] - fm);
        float e1 = __expf(acc[mi * 8 + ni][rr * 2 + 1] - fm);
        s += e0 + e1;
        float h0 = __bfloat162float(__float2bfloat16(e0));
        float h1 = __bfloat162float(__float2bfloat16(e1));
        const uint32_t sw = SWZ((uint32_t)(m * 128 + (ni * 8 + ec) * 2));
        *(uint32_t*)(sm + AT_PHI + ppan + sw) = pack2(h0, h1);
        *(uint32_t*)(sm + AT_PLO + ppan + sw) = pack2(e0 - h0, e1 - h1);
      }
      s += __shfl_xor_sync(0xffffffffu, s, 1);
      s += __shfl_xor_sync(0xffffffffu, s, 2);
      if ((lane & 3) == 0) REDS[wcol * 64 + m] = s;
    }
  __syncthreads();

  if (wcol == 0 && (lane & 3) == 0) {
#pragma unroll
    for (int mi = 0; mi < 2; mi++)
#pragma unroll
      for (int rr = 0; rr < 2; rr++) {
        const int m = mw + mi * 16 + rr * 8 + er;
        RINV[m] = 1.0f / (REDS[m] + REDS[64 + m] + REDS[128 + m] + REDS[192 + m]);
      }
  }
  __syncthreads();

  const int nw2 = (wid & 3) * 16;
  float accv[4][4];
#pragma unroll
  for (int i = 0; i < 4; i++)
#pragma unroll
    for (int j = 0; j < 4; j++) accv[i][j] = 0.f;

#pragma unroll
  for (int pp = 0; pp < 4; pp++) {
    const uint32_t pb = (uint32_t)pp * 8192;
#pragma unroll
    for (int ks = 0; ks < 4; ks++) {
      const uint32_t koff = (uint32_t)(ks * 32 + lkb);
      uint32_t ph[2][4], pl[2][4];
#pragma unroll
      for (int mi = 0; mi < 2; mi++) {
        const uint32_t off = (uint32_t)((mw + mi * 16 + lrow) * 128) + koff;
        ldsm4(ph[mi], sbase + AT_PHI + pb + SWZ(off));
        ldsm4(pl[mi], sbase + AT_PLO + pb + SWZ(off));
      }
      uint32_t vh[4], vl[4];
      {
        const uint32_t off = (uint32_t)((nw2 + lrow) * 128) + koff;
        ldsm4(vh, sbase + AT_VHI + pb + SWZ(off));
        ldsm4(vl, sbase + AT_VLO + pb + SWZ(off));
      }
#pragma unroll
      for (int ni = 0; ni < 2; ni++) {
        const uint32_t b0 = vh[ni], b1 = vh[2 + ni];
        const uint32_t c0 = vl[ni], c1 = vl[2 + ni];
#pragma unroll
        for (int mi = 0; mi < 2; mi++) {
          mma_bf16(accv[mi * 2 + ni], ph[mi], b0, b1);
          mma_bf16(accv[mi * 2 + ni], ph[mi], c0, c1);
          mma_bf16(accv[mi * 2 + ni], pl[mi], b0, b1);
        }
      }
    }
  }

  float* ctxbase = g_ctx + ((size_t)bb*SEQ + seg*SEG + qt*64)*EMB + hh*64;
#pragma unroll
  for (int mi = 0; mi < 2; mi++) {
#pragma unroll
    for (int rr = 0; rr < 2; rr++) {
      const int m = mw + mi * 16 + rr * 8 + er;
      const float iv = RINV[m];
#pragma unroll
      for (int ni = 0; ni < 2; ni++) {
        const int d = nw2 + ni * 8 + ec;
        float2 v;
        v.x = accv[mi * 2 + ni][rr * 2 + 0] * iv;
        v.y = accv[mi * 2 + ni][rr * 2 + 1] * iv;
        *(float2*)(ctxbase + (size_t)m * EMB + d) = v;
      }
    }
  }
}

// ===========================================================================
extern "C" void kernel_launch(void* const* d_in, const int* in_sizes, int n_in,
                              void* d_out, int out_size) {
  const float* x  = (const float*)d_in[0];
  const float* Wq = (const float*)d_in[1];
  const float* bq = (const float*)d_in[2];
  const float* Wk = (const float*)d_in[3];
  const float* bk = (const float*)d_in[4];
  const float* Wv = (const float*)d_in[5];
  const float* bv = (const float*)d_in[6];
  const float* Wo = (const float*)d_in[7];
  const float* bo = (const float*)d_in[8];
  float* out = (float*)d_out;

  cudaFuncSetAttribute(gemm_hmma_kernel,
                       cudaFuncAttributeMaxDynamicSharedMemorySize, GEMM_SMEM);
  cudaFuncSetAttribute(attn_kernel,
                       cudaFuncAttributeMaxDynamicSharedMemorySize, ATTN_SMEM);

  dim3 gqkv(6, 32, 3);
  gemm_hmma_kernel<<<gqkv, 256, GEMM_SMEM>>>(x, Wq, bq, Wk, bk, Wv, bv,
                                             nullptr, 0);

  attn_kernel<<<768, 256, ATTN_SMEM>>>();

  dim3 gout(6, 32, 1);
  gemm_hmma_kernel<<<gout, 256, GEMM_SMEM>>>(nullptr, Wo, bo, Wo, bo, Wo, bo,
                                             out, 1);
}

// round 12
// speedup vs baseline: 1.1805x; 1.1805x over previous
#include <cuda_runtime.h>
#include <cuda_bf16.h>
#include <cstdint>

#define NUM_HEADS 12
#define HEAD_DIM  64
#define SEQ       2048
#define BATCH     2
#define EMB       768
#define SEG       256
#define KDIM      768

// Scratch — EXACT R4/R8/R9 set (proven to pass the allocation guard)
__device__ float g_q[BATCH*NUM_HEADS*SEQ*HEAD_DIM];
__device__ float g_k[BATCH*NUM_HEADS*SEQ*HEAD_DIM];
__device__ float g_v[BATCH*NUM_HEADS*SEQ*HEAD_DIM];
__device__ float g_ctx[BATCH*SEQ*EMB];

// ===========================================================================
// Warp-level MMA helpers (compute_100-safe: sm_80-era PTX)
// ===========================================================================
__device__ __forceinline__ uint32_t smem_u32(const void* p) {
  uint32_t a;
  asm("{ .reg .u64 t; cvta.to.shared.u64 t, %1; cvt.u32.u64 %0, t; }" : "=r"(a) : "l"(p));
  return a;
}
__device__ __forceinline__ void ldsm4(uint32_t* r, uint32_t addr) {
  asm volatile("ldmatrix.sync.aligned.m8n8.x4.shared.b16 {%0,%1,%2,%3}, [%4];"
               : "=r"(r[0]), "=r"(r[1]), "=r"(r[2]), "=r"(r[3]) : "r"(addr));
}
__device__ __forceinline__ void ldsm4t(uint32_t* r, uint32_t addr) {
  asm volatile("ldmatrix.sync.aligned.m8n8.x4.trans.shared.b16 {%0,%1,%2,%3}, [%4];"
               : "=r"(r[0]), "=r"(r[1]), "=r"(r[2]), "=r"(r[3]) : "r"(addr));
}
__device__ __forceinline__ void mma_bf16(float* d, const uint32_t* a,
                                         uint32_t b0, uint32_t b1) {
  asm volatile(
      "mma.sync.aligned.m16n8k16.row.col.f32.bf16.bf16.f32 "
      "{%0,%1,%2,%3}, {%4,%5,%6,%7}, {%8,%9}, {%0,%1,%2,%3};"
      : "+f"(d[0]), "+f"(d[1]), "+f"(d[2]), "+f"(d[3])
      : "r"(a[0]), "r"(a[1]), "r"(a[2]), "r"(a[3]), "r"(b0), "r"(b1));
}

#define SWZ(off) ((off) ^ (((off) >> 3) & 0x70))

__device__ __forceinline__ uint32_t pack2(float a, float b) {
  __nv_bfloat162 p = __halves2bfloat162(__float2bfloat16(a), __float2bfloat16(b));
  return *reinterpret_cast<uint32_t*>(&p);
}

// ===========================================================================
// GEMM (R8-proven local optimum, untouched): C = A*W^T + bias, split-bf16
// 3-pass, single 64KB smem buffer, register prefetch of chunk c+1.
// ===========================================================================
#define GK      64
#define NCHUNK  (KDIM / GK)            // 12
#define OFF_AHI 0
#define OFF_ALO 16384
#define OFF_BHI 32768
#define OFF_BLO 49152
#define GEMM_SMEM 65536

__global__ __launch_bounds__(256) void gemm_hmma_kernel(
    const float* __restrict__ A0,
    const float* __restrict__ W0, const float* __restrict__ b0,
    const float* __restrict__ W1, const float* __restrict__ b1,
    const float* __restrict__ W2, const float* __restrict__ b2,
    float* __restrict__ dout, int mode) {
  extern __shared__ char sm[];
  const uint32_t sbase = smem_u32(sm);
  const int tid  = threadIdx.x;
  const int wid  = tid >> 5;
  const int lane = tid & 31;
  const int m0 = blockIdx.y * 128;
  const int n0 = blockIdx.x * 128;
  const int z  = blockIdx.z;

  const float* A    = (mode == 1) ? g_ctx : A0;
  const float* W    = (z == 0) ? W0 : (z == 1) ? W1 : W2;
  const float* bias = (z == 0) ? b0 : (z == 1) ? b1 : b2;
  float* outp = (mode == 1) ? dout : ((z == 0) ? g_q : (z == 1) ? g_k : g_v);

  const int r  = tid >> 1;
  const int cb = (tid & 1) * 32;
  const float* Ap = A + (size_t)(m0 + r) * KDIM + cb;
  const float* Wp = W + (size_t)(n0 + r) * KDIM + cb;

  const int mw = (wid >> 1) * 32;
  const int nw = (wid & 1) * 64;
  const int lrow = lane & 15;
  const int lkb  = (lane >> 4) * 16;

  float acc[16][4];
#pragma unroll
  for (int i = 0; i < 16; i++)
#pragma unroll
    for (int j = 0; j < 4; j++) acc[i][j] = 0.f;

  float4 pa[8], pw[8];
#pragma unroll
  for (int u = 0; u < 8; u++) {
    pa[u] = *(const float4*)(Ap + u * 4);
    pw[u] = *(const float4*)(Wp + u * 4);
  }

  for (int c = 0; c < NCHUNK; c++) {
#pragma unroll
    for (int u = 0; u < 8; u++) {
      const float4 av = pa[u];
      const float4 wv = pw[u];
      const uint32_t sw = SWZ((uint32_t)(r * 128 + (cb + u * 4) * 2));

      float ahx = __bfloat162float(__float2bfloat16(av.x));
      float ahy = __bfloat162float(__float2bfloat16(av.y));
      float ahz = __bfloat162float(__float2bfloat16(av.z));
      float ahw = __bfloat162float(__float2bfloat16(av.w));
      *(uint2*)(sm + OFF_AHI + sw) = make_uint2(pack2(ahx, ahy), pack2(ahz, ahw));
      *(uint2*)(sm + OFF_ALO + sw) =
          make_uint2(pack2(av.x - ahx, av.y - ahy), pack2(av.z - ahz, av.w - ahw));

      float whx = __bfloat162float(__float2bfloat16(wv.x));
      float why = __bfloat162float(__float2bfloat16(wv.y));
      float whz = __bfloat162float(__float2bfloat16(wv.z));
      float whw = __bfloat162float(__float2bfloat16(wv.w));
      *(uint2*)(sm + OFF_BHI + sw) = make_uint2(pack2(whx, why), pack2(whz, whw));
      *(uint2*)(sm + OFF_BLO + sw) =
          make_uint2(pack2(wv.x - whx, wv.y - why), pack2(wv.z - whz, wv.w - whw));
    }
    __syncthreads();

    if (c + 1 < NCHUNK) {
#pragma unroll
      for (int u = 0; u < 8; u++) {
        pa[u] = *(const float4*)(Ap + (c + 1) * GK + u * 4);
        pw[u] = *(const float4*)(Wp + (c + 1) * GK + u * 4);
      }
    }

#pragma unroll
    for (int ks = 0; ks < 4; ks++) {
      const uint32_t koff = (uint32_t)(ks * 32 + lkb);
      uint32_t ah[2][4], al[2][4];
#pragma unroll
      for (int mi = 0; mi < 2; mi++) {
        const uint32_t off = (uint32_t)((mw + mi * 16 + lrow) * 128) + koff;
        ldsm4(ah[mi], sbase + OFF_AHI + SWZ(off));
        ldsm4(al[mi], sbase + OFF_ALO + SWZ(off));
      }
      uint32_t bh[4][4], bl[4][4];
#pragma unroll
      for (int nb = 0; nb < 4; nb++) {
        const uint32_t off = (uint32_t)((nw + nb * 16 + lrow) * 128) + koff;
        ldsm4(bh[nb], sbase + OFF_BHI + SWZ(off));
        ldsm4(bl[nb], sbase + OFF_BLO + SWZ(off));
      }
#pragma unroll
      for (int ni = 0; ni < 8; ni++) {
        const int nb = ni >> 1, sel = ni & 1;
        const uint32_t bh0 = bh[nb][sel], bh1 = bh[nb][2 + sel];
        const uint32_t bl0 = bl[nb][sel], bl1 = bl[nb][2 + sel];
#pragma unroll
        for (int mi = 0; mi < 2; mi++) {
          mma_bf16(acc[mi * 8 + ni], ah[mi], bh0, bh1);
          mma_bf16(acc[mi * 8 + ni], ah[mi], bl0, bl1);
          mma_bf16(acc[mi * 8 + ni], al[mi], bh0, bh1);
        }
      }
    }
    __syncthreads();
  }

  const int er = lane >> 2;
  const int ec = (lane & 3) * 2;
#pragma unroll
  for (int mi = 0; mi < 2; mi++) {
#pragma unroll
    for (int rr = 0; rr < 2; rr++) {
      const int m = m0 + mw + mi * 16 + rr * 8 + er;
      if (mode == 1) {
        float* orow = outp + (size_t)m * EMB;
#pragma unroll
        for (int ni = 0; ni < 8; ni++) {
          const int n = n0 + nw + ni * 8 + ec;
          float2 v;
          v.x = acc[mi * 8 + ni][rr * 2 + 0] + bias[n];
          v.y = acc[mi * 8 + ni][rr * 2 + 1] + bias[n + 1];
          *(float2*)(orow + n) = v;
        }
      } else {
        const int b = m >> 11;
        const int s = m & 2047;
#pragma unroll
        for (int ni = 0; ni < 8; ni++) {
          const int n = n0 + nw + ni * 8 + ec;
          const int h = n >> 6;
          const int d = n & 63;
          float2 v;
          v.x = acc[mi * 8 + ni][rr * 2 + 0] + bias[n];
          v.y = acc[mi * 8 + ni][rr * 2 + 1] + bias[n + 1];
          *(float2*)(outp + (((size_t)b * NUM_HEADS + h) * SEQ + s) * HEAD_DIM + d) = v;
        }
      }
    }
  }
}

// ===========================================================================
// HMMA attention (R9 base). Change vs R9: V staged ROW-MAJOR like K
// (vectorized stores, no scalar transpose); PV loads V B-fragments via
// ldmatrix.x4.trans (canonical row-major-B path).
// ===========================================================================
#define AT_QHI  0
#define AT_QLO  8192
#define AT_KHI  16384
#define AT_KLO  49152
#define AT_PHI  81920
#define AT_PLO  114688
#define AT_VHI  147456                 // V row-major [j=256][128B] hi
#define AT_VLO  180224                 // V row-major lo
#define AT_REDM 212992
#define AT_REDS 214016
#define AT_RINV 215040
#define ATTN_SMEM 215296

__global__ __launch_bounds__(256) void attn_kernel() {
  extern __shared__ char sm[];
  const uint32_t sbase = smem_u32(sm);
  float* REDM = (float*)(sm + AT_REDM);
  float* REDS = (float*)(sm + AT_REDS);
  float* RINV = (float*)(sm + AT_RINV);

  const int tid  = threadIdx.x;
  const int wid  = tid >> 5;
  const int lane = tid & 31;
  int bx = blockIdx.x;
  const int qt  = bx & 3;   bx >>= 2;
  const int seg = bx & 7;   bx >>= 3;
  const int hh  = bx % NUM_HEADS;
  const int bb  = bx / NUM_HEADS;

  const size_t head_off = (((size_t)bb*NUM_HEADS + hh)*SEQ + seg*SEG) * HEAD_DIM;
  const float* qbase = g_q + head_off + (size_t)qt*64*HEAD_DIM;
  const float* kbase = g_k + head_off;
  const float* vbase = g_v + head_off;

  // ---- stage Q (scaled 0.125) hi/lo ----
  {
    const int r  = tid >> 2;
    const int c0 = (tid & 3) * 16;
#pragma unroll
    for (int u = 0; u < 4; u++) {
      float4 v = *(const float4*)(qbase + r * 64 + c0 + u * 4);
      v.x *= 0.125f; v.y *= 0.125f; v.z *= 0.125f; v.w *= 0.125f;
      const uint32_t sw = SWZ((uint32_t)(r * 128 + (c0 + u * 4) * 2));
      float hx = __bfloat162float(__float2bfloat16(v.x));
      float hy = __bfloat162float(__float2bfloat16(v.y));
      float hz = __bfloat162float(__float2bfloat16(v.z));
      float hw = __bfloat162float(__float2bfloat16(v.w));
      *(uint2*)(sm + AT_QHI + sw) = make_uint2(pack2(hx, hy), pack2(hz, hw));
      *(uint2*)(sm + AT_QLO + sw) =
          make_uint2(pack2(v.x - hx, v.y - hy), pack2(v.z - hz, v.w - hw));
    }
  }
  // ---- stage K and V rows (one each per thread), hi/lo, vectorized ----
  {
    const int j = tid;
#pragma unroll
    for (int u = 0; u < 16; u++) {
      const uint32_t sw = SWZ((uint32_t)(j * 128 + u * 8));
      float4 v = *(const float4*)(kbase + j * 64 + u * 4);
      float hx = __bfloat162float(__float2bfloat16(v.x));
      float hy = __bfloat162float(__float2bfloat16(v.y));
      float hz = __bfloat162float(__float2bfloat16(v.z));
      float hw = __bfloat162float(__float2bfloat16(v.w));
      *(uint2*)(sm + AT_KHI + sw) = make_uint2(pack2(hx, hy), pack2(hz, hw));
      *(uint2*)(sm + AT_KLO + sw) =
          make_uint2(pack2(v.x - hx, v.y - hy), pack2(v.z - hz, v.w - hw));

      float4 w = *(const float4*)(vbase + j * 64 + u * 4);
      float gx = __bfloat162float(__float2bfloat16(w.x));
      float gy = __bfloat162float(__float2bfloat16(w.y));
      float gz = __bfloat162float(__float2bfloat16(w.z));
      float gw = __bfloat162float(__float2bfloat16(w.w));
      *(uint2*)(sm + AT_VHI + sw) = make_uint2(pack2(gx, gy), pack2(gz, gw));
      *(uint2*)(sm + AT_VLO + sw) =
          make_uint2(pack2(w.x - gx, w.y - gy), pack2(w.z - gz, w.w - gw));
    }
  }
  __syncthreads();

  // ---- scores: S(64x256) = Q @ K^T, 3-pass, warp tile 32x64 ----
  const int mw = (wid >> 2) * 32;
  const int nw = (wid & 3) * 64;
  const int lrow = lane & 15;
  const int lkb  = (lane >> 4) * 16;

  float acc[16][4];
#pragma unroll
  for (int i = 0; i < 16; i++)
#pragma unroll
    for (int j = 0; j < 4; j++) acc[i][j] = 0.f;

#pragma unroll
  for (int ks = 0; ks < 4; ks++) {
    const uint32_t koff = (uint32_t)(ks * 32 + lkb);
    uint32_t ah[2][4], al[2][4];
#pragma unroll
    for (int mi = 0; mi < 2; mi++) {
      const uint32_t off = (uint32_t)((mw + mi * 16 + lrow) * 128) + koff;
      ldsm4(ah[mi], sbase + AT_QHI + SWZ(off));
      ldsm4(al[mi], sbase + AT_QLO + SWZ(off));
    }
    uint32_t bh[4][4], bl[4][4];
#pragma unroll
    for (int nb = 0; nb < 4; nb++) {
      const uint32_t off = (uint32_t)((nw + nb * 16 + lrow) * 128) + koff;
      ldsm4(bh[nb], sbase + AT_KHI + SWZ(off));
      ldsm4(bl[nb], sbase + AT_KLO + SWZ(off));
    }
#pragma unroll
    for (int ni = 0; ni < 8; ni++) {
      const int nb = ni >> 1, sel = ni & 1;
      const uint32_t bh0 = bh[nb][sel], bh1 = bh[nb][2 + sel];
      const uint32_t bl0 = bl[nb][sel], bl1 = bl[nb][2 + sel];
#pragma unroll
      for (int mi = 0; mi < 2; mi++) {
        mma_bf16(acc[mi * 8 + ni], ah[mi], bh0, bh1);
        mma_bf16(acc[mi * 8 + ni], ah[mi], bl0, bl1);
        mma_bf16(acc[mi * 8 + ni], al[mi], bh0, bh1);
      }
    }
  }

  // ---- softmax ----
  const int er = lane >> 2;
  const int ec = (lane & 3) * 2;
  const int wcol = wid & 3;

#pragma unroll
  for (int mi = 0; mi < 2; mi++)
#pragma unroll
    for (int rr = 0; rr < 2; rr++) {
      float m = -1e30f;
#pragma unroll
      for (int ni = 0; ni < 8; ni++) {
        m = fmaxf(m, acc[mi * 8 + ni][rr * 2 + 0]);
        m = fmaxf(m, acc[mi * 8 + ni][rr * 2 + 1]);
      }
      m = fmaxf(m, __shfl_xor_sync(0xffffffffu, m, 1));
      m = fmaxf(m, __shfl_xor_sync(0xffffffffu, m, 2));
      if ((lane & 3) == 0)
        REDM[wcol * 64 + mw + mi * 16 + rr * 8 + er] = m;
    }
  __syncthreads();

  const uint32_t ppan = (uint32_t)wcol * 8192;
#pragma unroll
  for (int mi = 0; mi < 2; mi++)
#pragma unroll
    for (int rr = 0; rr < 2; rr++) {
      const int m = mw + mi * 16 + rr * 8 + er;
      float fm = fmaxf(fmaxf(REDM[m], REDM[64 + m]),
                       fmaxf(REDM[128 + m], REDM[192 + m]));
      float s = 0.f;
#pragma unroll
      for (int ni = 0; ni < 8; ni++) {
        float e0 = __expf(acc[mi * 8 + ni][rr * 2 + 0] - fm);
        float e1 = __expf(acc[mi * 8 + ni][rr * 2 + 1] - fm);
        s += e0 + e1;
        float h0 = __bfloat162float(__float2bfloat16(e0));
        float h1 = __bfloat162float(__float2bfloat16(e1));
        const uint32_t sw = SWZ((uint32_t)(m * 128 + (ni * 8 + ec) * 2));
        *(uint32_t*)(sm + AT_PHI + ppan + sw) = pack2(h0, h1);
        *(uint32_t*)(sm + AT_PLO + ppan + sw) = pack2(e0 - h0, e1 - h1);
      }
      s += __shfl_xor_sync(0xffffffffu, s, 1);
      s += __shfl_xor_sync(0xffffffffu, s, 2);
      if ((lane & 3) == 0) REDS[wcol * 64 + m] = s;
    }
  __syncthreads();

  if (wcol == 0 && (lane & 3) == 0) {
#pragma unroll
    for (int mi = 0; mi < 2; mi++)
#pragma unroll
      for (int rr = 0; rr < 2; rr++) {
        const int m = mw + mi * 16 + rr * 8 + er;
        RINV[m] = 1.0f / (REDS[m] + REDS[64 + m] + REDS[128 + m] + REDS[192 + m]);
      }
  }
  __syncthreads();

  // ---- PV: ctx(64x64) = P(64x256) @ V, V via ldmatrix.trans ----
  const int nw2 = (wid & 3) * 16;
  // trans lane mapping: tile order (k-lo,n0),(k-lo,n1),(k-hi,n0),(k-hi,n1)
  const int trow = (lane & 7) + ((lane >> 4) << 3);   // row within 16 j-rows
  const int tcol = ((lane >> 3) & 1) << 3;            // d sub-block 0/8
  float accv[4][4];
#pragma unroll
  for (int i = 0; i < 4; i++)
#pragma unroll
    for (int j = 0; j < 4; j++) accv[i][j] = 0.f;

#pragma unroll
  for (int pp = 0; pp < 4; pp++) {
    const uint32_t pb = (uint32_t)pp * 8192;
#pragma unroll
    for (int ks = 0; ks < 4; ks++) {
      const uint32_t koff = (uint32_t)(ks * 32 + lkb);
      uint32_t ph[2][4], pl[2][4];
#pragma unroll
      for (int mi = 0; mi < 2; mi++) {
        const uint32_t off = (uint32_t)((mw + mi * 16 + lrow) * 128) + koff;
        ldsm4(ph[mi], sbase + AT_PHI + pb + SWZ(off));
        ldsm4(pl[mi], sbase + AT_PLO + pb + SWZ(off));
      }
      uint32_t vh[4], vl[4];
      {
        const int jg = pp * 64 + ks * 16 + trow;      // global V row
        const uint32_t off = SWZ((uint32_t)(jg * 128 + (nw2 + tcol) * 2));
        ldsm4t(vh, sbase + AT_VHI + off);
        ldsm4t(vl, sbase + AT_VLO + off);
      }
#pragma unroll
      for (int ni = 0; ni < 2; ni++) {
        const uint32_t b0 = vh[ni], b1 = vh[2 + ni];
        const uint32_t c0 = vl[ni], c1 = vl[2 + ni];
#pragma unroll
        for (int mi = 0; mi < 2; mi++) {
          mma_bf16(accv[mi * 2 + ni], ph[mi], b0, b1);
          mma_bf16(accv[mi * 2 + ni], ph[mi], c0, c1);
          mma_bf16(accv[mi * 2 + ni], pl[mi], b0, b1);
        }
      }
    }
  }

  // ---- epilogue: normalize, scatter to (B,S,E) ----
  float* ctxbase = g_ctx + ((size_t)bb*SEQ + seg*SEG + qt*64)*EMB + hh*64;
#pragma unroll
  for (int mi = 0; mi < 2; mi++) {
#pragma unroll
    for (int rr = 0; rr < 2; rr++) {
      const int m = mw + mi * 16 + rr * 8 + er;
      const float iv = RINV[m];
#pragma unroll
      for (int ni = 0; ni < 2; ni++) {
        const int d = nw2 + ni * 8 + ec;
        float2 v;
        v.x = accv[mi * 2 + ni][rr * 2 + 0] * iv;
        v.y = accv[mi * 2 + ni][rr * 2 + 1] * iv;
        *(float2*)(ctxbase + (size_t)m * EMB + d) = v;
      }
    }
  }
}

// ===========================================================================
extern "C" void kernel_launch(void* const* d_in, const int* in_sizes, int n_in,
                              void* d_out, int out_size) {
  const float* x  = (const float*)d_in[0];
  const float* Wq = (const float*)d_in[1];
  const float* bq = (const float*)d_in[2];
  const float* Wk = (const float*)d_in[3];
  const float* bk = (const float*)d_in[4];
  const float* Wv = (const float*)d_in[5];
  const float* bv = (const float*)d_in[6];
  const float* Wo = (const float*)d_in[7];
  const float* bo = (const float*)d_in[8];
  float* out = (float*)d_out;

  cudaFuncSetAttribute(gemm_hmma_kernel,
                       cudaFuncAttributeMaxDynamicSharedMemorySize, GEMM_SMEM);
  cudaFuncSetAttribute(attn_kernel,
                       cudaFuncAttributeMaxDynamicSharedMemorySize, ATTN_SMEM);

  dim3 gqkv(6, 32, 3);
  gemm_hmma_kernel<<<gqkv, 256, GEMM_SMEM>>>(x, Wq, bq, Wk, bk, Wv, bv,
                                             nullptr, 0);

  attn_kernel<<<768, 256, ATTN_SMEM>>>();

  dim3 gout(6, 32, 1);
  gemm_hmma_kernel<<<gout, 256, GEMM_SMEM>>>(nullptr, Wo, bo, Wo, bo, Wo, bo,
                                             out, 1);
}